// round 13
// baseline (speedup 1.0000x reference)
#include <cuda_runtime.h>
#include <cstdint>

// Occupancy connectivity loss over a 385^3 fp32 grid, C order:
//   f = x*385^2 + y*385 + z
// Warp-autonomous, cp.async-pipelined. Each warp owns a 5(y) x 31(z) tile and
// marches 49 planes in x. Per plane: 6 rows (5 owned + 1 y-halo) streamed
// gmem->smem via cp.async into a depth-4 per-warp ring (3 planes in flight,
// no register scoreboard stalls). Compute reads its own copied column back:
//   y-diff: in-register between adjacent row registers
//   z-diff: shfl_down(row, 1)
//   x-diff: current rows vs previous plane's rows (kept in registers)
// Boundary handling via clamped duplicate loads (diffs contribute exact 0).

#define ROW    385u
#define PLANE  148225u
#define NZT    13u                 // z tiles: zb = 0,31,...,372
#define NYG    77u                 // y groups of 5 owned rows (5*77 = 385)
#define XC     8u                  // x chunks of 48 pairs (49 planes)
#define WPB    8u
#define NTASKS (NZT * NYG * XC)    // 8008 warp tasks
#define NBLOCKS (NTASKS / WPB)     // 1001
#define DPTH   4                   // ring depth (planes)

__device__ double   g_part[NBLOCKS];
__device__ unsigned g_count = 0;

__global__ void __launch_bounds__(256, 7)
occ_main(const float* __restrict__ occ, float* __restrict__ out) {
    const unsigned wid  = threadIdx.x >> 5;
    const unsigned lane = threadIdx.x & 31u;

    const unsigned w  = blockIdx.x * WPB + wid;
    const unsigned zt = w % NZT;
    const unsigned r1 = w / NZT;
    const unsigned yg = r1 % NYG;
    const unsigned xc = r1 / NYG;

    const unsigned zb = zt * 31u;
    const unsigned z  = min(zb + lane, 384u);       // clamp: dup loads harmless
    const unsigned yb = yg * 5u;

    const bool lastzt = (zt == NZT - 1u);
    const bool yxm = lane < (lastzt ? 13u : 31u);   // owned z columns
    const bool zm  = lane < (lastzt ? 12u : 31u);   // owned z pairs
    const bool lastc = (xc == XC - 1u);
    // last y group: halo row duplicates y=384 -> y-diff contributes 0
    const unsigned off5 = (yg == NYG - 1u) ? 4u * ROW : 5u * ROW;

    __shared__ float ring[WPB][DPTH][6][32];        // 24 KB / block

    const float* p = occ + (size_t)yb * ROW + z + (size_t)(48u * xc) * PLANE;

    // byte address of this thread's column at slot 0, row 0
    uint32_t sb = (uint32_t)__cvta_generic_to_shared(&ring[wid][0][0][lane]);
    // slot stride = 6*32*4 = 768 B, row stride = 128 B

    int jp = 0;   // next plane (chunk-relative) to issue
    #define ISSUE() do {                                                    \
        if (jp <= 48) {                                                     \
            uint32_t sa = sb + (uint32_t)(jp & 3) * 768u;                   \
            asm volatile("cp.async.ca.shared.global [%0], [%1], 4;\n"       \
                         :: "r"(sa),        "l"(p));                        \
            asm volatile("cp.async.ca.shared.global [%0], [%1], 4;\n"       \
                         :: "r"(sa + 128u), "l"(p + ROW));                  \
            asm volatile("cp.async.ca.shared.global [%0], [%1], 4;\n"       \
                         :: "r"(sa + 256u), "l"(p + 2u * ROW));             \
            asm volatile("cp.async.ca.shared.global [%0], [%1], 4;\n"       \
                         :: "r"(sa + 384u), "l"(p + 3u * ROW));             \
            asm volatile("cp.async.ca.shared.global [%0], [%1], 4;\n"       \
                         :: "r"(sa + 512u), "l"(p + 4u * ROW));             \
            asm volatile("cp.async.ca.shared.global [%0], [%1], 4;\n"       \
                         :: "r"(sa + 640u), "l"(p + off5));                 \
        }                                                                   \
        asm volatile("cp.async.commit_group;\n");                           \
        p += PLANE; ++jp;                                                   \
    } while(0)

    // prime: planes 0..2 in flight
    ISSUE(); ISSUE(); ISSUE();

    float s0 = 0.f, s1 = 0.f;
    float pv0=0.f,pv1=0.f,pv2=0.f,pv3=0.f,pv4=0.f;

    for (int j = 0; j <= 48; ++j) {
        // groups committed so far = j+3; allow 2 newest incomplete
        // -> plane j's group is complete before we read it
        asm volatile("cp.async.wait_group 2;\n" ::: "memory");

        const float* sr = &ring[wid][j & 3][0][lane];
        float c0 = sr[0];   float c1 = sr[32];  float c2 = sr[64];
        float c3 = sr[96];  float c4 = sr[128]; float c5 = sr[160];

        if (j > 0 && yxm) {   // x-diffs pair (j-1, j)
            s1 += fabsf(c0 - pv0) + fabsf(c1 - pv1) + fabsf(c2 - pv2)
                + fabsf(c3 - pv3) + fabsf(c4 - pv4);
        }
        if (j < 48 || lastc) {   // z/y diffs for plane j
            float z0 = __shfl_down_sync(0xffffffffu, c0, 1);
            float z1 = __shfl_down_sync(0xffffffffu, c1, 1);
            float z2 = __shfl_down_sync(0xffffffffu, c2, 1);
            float z3 = __shfl_down_sync(0xffffffffu, c3, 1);
            float z4 = __shfl_down_sync(0xffffffffu, c4, 1);
            if (zm)
                s0 += fabsf(z0 - c0) + fabsf(z1 - c1) + fabsf(z2 - c2)
                    + fabsf(z3 - c3) + fabsf(z4 - c4);
            if (yxm)
                s0 += fabsf(c1 - c0) + fabsf(c2 - c1) + fabsf(c3 - c2)
                    + fabsf(c4 - c3) + fabsf(c5 - c4);
        }
        pv0 = c0; pv1 = c1; pv2 = c2; pv3 = c3; pv4 = c4;

        ISSUE();   // plane j+3 (predicated; empty groups keep the count law)
    }

    // ---- block reduction ----
    float s = s0 + s1;
    #pragma unroll
    for (int o = 16; o > 0; o >>= 1)
        s += __shfl_down_sync(0xffffffffu, s, o);

    __shared__ float    ws[WPB];
    __shared__ unsigned islast_s;
    if (lane == 0u) ws[wid] = s;
    __syncthreads();
    if (threadIdx.x == 0u) {
        float t = 0.f;
        #pragma unroll
        for (unsigned i = 0; i < WPB; ++i) t += ws[i];
        g_part[blockIdx.x] = (double)t;
        __threadfence();
        unsigned old = atomicAdd(&g_count, 1u);
        islast_s = (old == NBLOCKS - 1u) ? 1u : 0u;
    }
    __syncthreads();

    // ---- last block folds partials (single launch total) ----
    if (islast_s) {
        double d = 0.0;
        for (unsigned i = threadIdx.x; i < NBLOCKS; i += 256u)
            d += g_part[i];
        __shared__ double dsm[256];
        dsm[threadIdx.x] = d;
        __syncthreads();
        #pragma unroll
        for (int st = 128; st > 0; st >>= 1) {
            if ((int)threadIdx.x < st) dsm[threadIdx.x] += dsm[threadIdx.x + st];
            __syncthreads();
        }
        if (threadIdx.x == 0u) {
            out[0] = (float)dsm[0];
            g_count = 0u;   // reset for next graph replay
        }
    }
}

extern "C" void kernel_launch(void* const* d_in, const int* in_sizes, int n_in,
                              void* d_out, int out_size) {
    const float* occ = (const float*)d_in[0];
    float* out = (float*)d_out;
    occ_main<<<NBLOCKS, 256>>>(occ, out);
}

// round 14
// speedup vs baseline: 1.3099x; 1.3099x over previous
#include <cuda_runtime.h>
#include <cstdint>

// Occupancy connectivity loss over a 385^3 fp32 grid, C order:
//   f = x*385^2 + y*385 + z
// Bulk-async pipeline: block owns 7 y-rows (+1 halo) and marches 49 planes.
// The 8 rows of one plane are CONTIGUOUS in memory -> ONE cp.async.bulk
// (12.3 KB) per plane into a 4-slot smem ring driven by mbarriers (3 planes
// in flight). Compute (7 worker warps, 1 row each):
//   x-diff: vs previous plane's values kept in registers (cprev[13])
//   z-diff: S[z+1] (conflict-free scalar LDS)
//   y-diff: S[z+ROW] (next row in slab, halo row included)
// Copy windows rounded to 16B; odd row offsets absorbed via off0=(x+yb)&3.

#define ROW    385u
#define PLANE  148225u
#define NYG    55
#define XC     8
#define NBLOCKS (NYG * XC)        // 440
#define NP     49                 // planes per chunk
#define SLABB  12352              // slab bytes (mult of 16, >= 8*385*4+12+pad)
#define SLABF  (SLABB / 4)
#define RINGOFF 64
#define SMEMSZ (RINGOFF + 4 * SLABB)   // 49472 B

__device__ double   g_part[NBLOCKS];
__device__ unsigned g_count = 0;

#define MBAR_INIT(a, c) \
    asm volatile("mbarrier.init.shared.b64 [%0], %1;" :: "r"(a), "r"(c) : "memory")
#define MBAR_EXPECT(a, b) \
    asm volatile("mbarrier.arrive.expect_tx.shared.b64 _, [%0], %1;" :: "r"(a), "r"(b) : "memory")
#define MBAR_ARRIVE(a) \
    asm volatile("mbarrier.arrive.shared.b64 _, [%0];" :: "r"(a) : "memory")
#define MBAR_WAIT(a, ph) do {                                                \
    unsigned _d;                                                             \
    do {                                                                     \
        asm volatile("{\n\t.reg .pred p;\n\t"                                \
            "mbarrier.try_wait.parity.acquire.cta.shared::cta.b64 p, [%1], %2, 0x989680;\n\t" \
            "selp.b32 %0, 1, 0, p;\n\t}"                                     \
            : "=r"(_d) : "r"(a), "r"(ph) : "memory");                        \
    } while (!_d); } while (0)

__global__ void __launch_bounds__(256)
occ_main(const float* __restrict__ occ, float* __restrict__ out) {
    extern __shared__ char smem[];
    const uint32_t sbase = (uint32_t)__cvta_generic_to_shared(smem);
    const uint32_t fullb = sbase;        // 4 x 8B full barriers
    const uint32_t emptb = sbase + 32;   // 4 x 8B empty barriers
    float* ring = (float*)(smem + RINGOFF);

    const int tid  = threadIdx.x;
    const unsigned wid  = (unsigned)tid >> 5;
    const unsigned lane = (unsigned)tid & 31u;

    const unsigned yg = blockIdx.x % NYG;
    const unsigned xc = blockIdx.x / NYG;
    const unsigned yb = yg * 7u;
    const unsigned as = 48u * xc;
    const bool  lastc = (xc == XC - 1);
    const unsigned nrows  = (yg == NYG - 1) ? 7u : 8u;
    const unsigned nbytes = nrows * ROW * 4u;

    if (tid == 0) {
        #pragma unroll
        for (int s = 0; s < 4; ++s) {
            MBAR_INIT(fullb + 8u * s, 1u);
            MBAR_INIT(emptb + 8u * s, 256u);
        }
    }
    __syncthreads();

    // one bulk copy per plane: rows yb..yb+nrows-1 of plane x are contiguous
    auto issue = [&](int j2) {
        const unsigned x   = as + (unsigned)j2;
        const char* srcf   = (const char*)(occ + (size_t)x * PLANE + (size_t)yb * ROW);
        const unsigned off = (unsigned)((x + yb) & 3u) * 4u;
        const char* srcb   = srcf - off;
        const unsigned sz  = (nbytes + off + 15u) & ~15u;
        const uint32_t mb  = fullb + 8u * (unsigned)(j2 & 3);
        const uint32_t dst = sbase + RINGOFF + (uint32_t)(j2 & 3) * SLABB;
        MBAR_EXPECT(mb, sz);
        asm volatile(
            "cp.async.bulk.shared::cta.global.mbarrier::complete_tx::bytes [%0], [%1], %2, [%3];"
            :: "r"(dst), "l"(srcb), "r"(sz), "r"(mb) : "memory");
    };

    if (tid == 0) { issue(0); issue(1); issue(2); }   // prime slots 0..2

    const unsigned yrow   = yb + wid;
    const bool     rowv   = (wid < 7u);               // worker warps own a row
    const bool     ypairv = rowv && (yrow < 384u);

    float cprev[13];
    float s0 = 0.f, s1 = 0.f;

    for (int j = 0; j < NP; ++j) {
        // producer: issue plane j+3 into slot (j+3)&3 (= released slot (j-1)&3)
        if (tid == 0 && j + 3 < NP) {
            if (j >= 1) MBAR_WAIT(emptb + 8u * (unsigned)((j - 1) & 3),
                                  (unsigned)(((j - 1) >> 2) & 1));
            issue(j + 3);
        }
        // consumers: wait plane j
        MBAR_WAIT(fullb + 8u * (unsigned)(j & 3), (unsigned)((j >> 2) & 1));

        if (rowv) {
            const unsigned x  = as + (unsigned)j;
            const float*   S  = ring + (size_t)(j & 3) * SLABF
                              + ((x + yb) & 3u) + (size_t)wid * ROW;
            const bool doZY = (j < NP - 1) || lastc;
            #pragma unroll
            for (int k = 0; k < 13; ++k) {
                const unsigned z = (unsigned)k * 32u + lane;
                const bool act = (z <= 384u);
                float c = 0.f;
                if (act) {
                    c = S[z];
                    if (doZY) {
                        if (z < 384u) s0 += fabsf(S[z + 1u]  - c);
                        if (ypairv)   s0 += fabsf(S[z + ROW] - c);
                    }
                    if (j > 0)        s1 += fabsf(c - cprev[k]);
                }
                cprev[k] = c;
            }
        }
        MBAR_ARRIVE(emptb + 8u * (unsigned)(j & 3));   // release slot j
    }

    // ---- block reduction ----
    float s = s0 + s1;
    #pragma unroll
    for (int o = 16; o > 0; o >>= 1)
        s += __shfl_down_sync(0xffffffffu, s, o);

    __shared__ float    ws[8];
    __shared__ unsigned islast_s;
    if (lane == 0u) ws[wid] = s;
    __syncthreads();
    if (tid == 0) {
        float t = 0.f;
        #pragma unroll
        for (int i = 0; i < 8; ++i) t += ws[i];
        g_part[blockIdx.x] = (double)t;
        __threadfence();
        unsigned old = atomicAdd(&g_count, 1u);
        islast_s = (old == NBLOCKS - 1u) ? 1u : 0u;
    }
    __syncthreads();

    // ---- last block folds partials (single launch total) ----
    if (islast_s) {
        double d = 0.0;
        for (unsigned i = (unsigned)tid; i < NBLOCKS; i += 256u)
            d += g_part[i];
        __shared__ double dsm[256];
        dsm[tid] = d;
        __syncthreads();
        #pragma unroll
        for (int st = 128; st > 0; st >>= 1) {
            if (tid < st) dsm[tid] += dsm[tid + st];
            __syncthreads();
        }
        if (tid == 0) {
            out[0] = (float)dsm[0];
            g_count = 0u;   // reset for next graph replay
        }
    }
}

extern "C" void kernel_launch(void* const* d_in, const int* in_sizes, int n_in,
                              void* d_out, int out_size) {
    const float* occ = (const float*)d_in[0];
    float* out = (float*)d_out;
    cudaFuncSetAttribute(occ_main, cudaFuncAttributeMaxDynamicSharedMemorySize, SMEMSZ);
    occ_main<<<NBLOCKS, 256, SMEMSZ>>>(occ, out);
}

// round 15
// speedup vs baseline: 1.3940x; 1.0642x over previous
#include <cuda_runtime.h>
#include <cstdint>

// Occupancy connectivity loss over a 385^3 fp32 grid, C order:
//   f = x*385^2 + y*385 + z
// Bulk-async pipeline: block owns 7 y-rows (+1 halo) and marches 25 planes.
// The 8 rows of one plane are CONTIGUOUS -> ONE cp.async.bulk (12.3 KB) per
// plane into a 3-slot smem ring driven by mbarriers (2 planes in flight).
// 6 blocks/SM (37 KB smem), 880 blocks = one full wave.
// Consumer (7 worker warps, 1 row each), branch-light:
//   k = 0..11: z = 32k+lane <= 383, all guards compile-time true
//   k = 12:    z = 384 (lane 0 only)
//   x-diff: vs previous plane's registers (cprev[13])
//   z-diff: S[z+1]; y-diff: S[z+ROW] (halo row in slab)

#define ROW    385u
#define PLANE  148225u
#define NYG    55
#define XC     16
#define NBLOCKS (NYG * XC)        // 880
#define NP     25                 // planes per chunk (24 x-pairs)
#define SLABB  12352              // slab bytes (16B mult, >= 8*385*4 + 12)
#define SLABF  (SLABB / 4)
#define RINGOFF 64
#define SMEMSZ (RINGOFF + 3 * SLABB)   // 37120 B -> 6 blocks/SM

__device__ double   g_part[NBLOCKS];
__device__ unsigned g_count = 0;

#define MBAR_INIT(a, c) \
    asm volatile("mbarrier.init.shared.b64 [%0], %1;" :: "r"(a), "r"(c) : "memory")
#define MBAR_EXPECT(a, b) \
    asm volatile("mbarrier.arrive.expect_tx.shared.b64 _, [%0], %1;" :: "r"(a), "r"(b) : "memory")
#define MBAR_ARRIVE(a) \
    asm volatile("mbarrier.arrive.shared.b64 _, [%0];" :: "r"(a) : "memory")
#define MBAR_WAIT(a, ph) do {                                                \
    unsigned _d;                                                             \
    do {                                                                     \
        asm volatile("{\n\t.reg .pred p;\n\t"                                \
            "mbarrier.try_wait.parity.acquire.cta.shared::cta.b64 p, [%1], %2, 0x989680;\n\t" \
            "selp.b32 %0, 1, 0, p;\n\t}"                                     \
            : "=r"(_d) : "r"(a), "r"(ph) : "memory");                        \
    } while (!_d); } while (0)

__global__ void __launch_bounds__(256, 6)
occ_main(const float* __restrict__ occ, float* __restrict__ out) {
    extern __shared__ char smem[];
    const uint32_t sbase = (uint32_t)__cvta_generic_to_shared(smem);
    const uint32_t fullb = sbase;        // 3 x 8B full barriers
    const uint32_t emptb = sbase + 24;   // 3 x 8B empty barriers
    float* ring = (float*)(smem + RINGOFF);

    const int tid  = threadIdx.x;
    const unsigned wid  = (unsigned)tid >> 5;
    const unsigned lane = (unsigned)tid & 31u;

    const unsigned yg = blockIdx.x % NYG;
    const unsigned xc = blockIdx.x / NYG;
    const unsigned yb = yg * 7u;
    const unsigned as = 24u * xc;
    const bool  lastc = (xc == XC - 1);
    const unsigned nrows  = (yg == NYG - 1) ? 7u : 8u;
    const unsigned nbytes = nrows * ROW * 4u;

    if (tid == 0) {
        #pragma unroll
        for (int s = 0; s < 3; ++s) {
            MBAR_INIT(fullb + 8u * s, 1u);
            MBAR_INIT(emptb + 8u * s, 256u);
        }
    }
    __syncthreads();

    auto issue = [&](int j2) {
        const unsigned x   = as + (unsigned)j2;
        const char* srcf   = (const char*)(occ + (size_t)x * PLANE + (size_t)yb * ROW);
        const unsigned off = (unsigned)((x + yb) & 3u) * 4u;
        const char* srcb   = srcf - off;
        const unsigned sz  = (nbytes + off + 15u) & ~15u;
        const int      sl  = j2 % 3;
        MBAR_EXPECT(fullb + 8u * sl, sz);
        asm volatile(
            "cp.async.bulk.shared::cta.global.mbarrier::complete_tx::bytes [%0], [%1], %2, [%3];"
            :: "r"(sbase + RINGOFF + (uint32_t)sl * SLABB), "l"(srcb), "r"(sz),
               "r"(fullb + 8u * sl) : "memory");
    };

    if (tid == 0) { issue(0); issue(1); }   // prime slots 0,1

    const unsigned yrow   = yb + wid;
    const bool     rowv   = (wid < 7u);
    const bool     ypairv = rowv && (yrow < 384u);

    float cprev[13];
    float s0 = 0.f, s1 = 0.f;

    for (int j = 0; j < NP; ++j) {
        const int sl = j % 3;
        // producer: issue plane j+2 into slot (j+2)%3 (= slot of plane j-1)
        if (tid == 0 && j + 2 < NP) {
            if (j >= 1)
                MBAR_WAIT(emptb + 8u * ((j - 1) % 3), (unsigned)(((j - 1) / 3) & 1));
            issue(j + 2);
        }
        MBAR_WAIT(fullb + 8u * sl, (unsigned)((j / 3) & 1));

        if (rowv) {
            const unsigned x = as + (unsigned)j;
            const float*   S = ring + (size_t)sl * SLABF
                             + ((x + yb) & 3u) + (size_t)wid * ROW + lane;
            if (j > 0) {   // x-diffs pair (j-1, j)
                #pragma unroll
                for (int k = 0; k < 12; ++k)
                    s1 += fabsf(S[32 * k] - cprev[k]);
                if (lane == 0u) s1 += fabsf(S[384] - cprev[12]);
            }
            if (j < NP - 1 || lastc) {   // z/y diffs for plane j
                #pragma unroll
                for (int k = 0; k < 12; ++k) {
                    float c = S[32 * k];
                    s0 += fabsf(S[32 * k + 1] - c);
                    if (ypairv) s0 += fabsf(S[32 * k + (int)ROW] - c);
                    cprev[k] = c;
                }
                float c12 = 0.f;
                if (lane == 0u) {
                    c12 = S[384];
                    if (ypairv) s0 += fabsf(S[384 + (int)ROW] - c12);
                }
                cprev[12] = c12;
            } else {       // last plane of a non-final chunk: refresh cprev only
                #pragma unroll
                for (int k = 0; k < 12; ++k) cprev[k] = S[32 * k];
                cprev[12] = (lane == 0u) ? S[384] : 0.f;
            }
        }
        MBAR_ARRIVE(emptb + 8u * sl);   // release slot j
    }

    // ---- block reduction ----
    float s = s0 + s1;
    #pragma unroll
    for (int o = 16; o > 0; o >>= 1)
        s += __shfl_down_sync(0xffffffffu, s, o);

    __shared__ float    ws[8];
    __shared__ unsigned islast_s;
    if (lane == 0u) ws[wid] = s;
    __syncthreads();
    if (tid == 0) {
        float t = 0.f;
        #pragma unroll
        for (int i = 0; i < 8; ++i) t += ws[i];
        g_part[blockIdx.x] = (double)t;
        __threadfence();
        unsigned old = atomicAdd(&g_count, 1u);
        islast_s = (old == NBLOCKS - 1u) ? 1u : 0u;
    }
    __syncthreads();

    // ---- last block folds partials (single launch total) ----
    if (islast_s) {
        double d = 0.0;
        for (unsigned i = (unsigned)tid; i < NBLOCKS; i += 256u)
            d += g_part[i];
        __shared__ double dsm[256];
        dsm[tid] = d;
        __syncthreads();
        #pragma unroll
        for (int st = 128; st > 0; st >>= 1) {
            if (tid < st) dsm[tid] += dsm[tid + st];
            __syncthreads();
        }
        if (tid == 0) {
            out[0] = (float)dsm[0];
            g_count = 0u;   // reset for next graph replay
        }
    }
}

extern "C" void kernel_launch(void* const* d_in, const int* in_sizes, int n_in,
                              void* d_out, int out_size) {
    const float* occ = (const float*)d_in[0];
    float* out = (float*)d_out;
    occ_main<<<NBLOCKS, 256, SMEMSZ>>>(occ, out);
}

// round 16
// speedup vs baseline: 1.7702x; 1.2699x over previous
#include <cuda_runtime.h>

// Occupancy connectivity loss over a 385^3 fp32 grid, C order:
//   f = x*385^2 + y*385 + z
// Warp-autonomous (R11) + stall-cover reordering: NO barriers, NO smem data.
// Each warp owns a 7(y) x 31(z) tile and marches 48 planes in x:
//   rows 0..6 owned, row 7 = y-halo (in registers)
//   lanes: z = zb + lane, zb = 31*ztile (tiles overlap by 1 column)
//   y-diff: in-register between adjacent row registers
//   z-diff: shfl_down(row, 1), lanes 0..30 accumulate
//   x-diff: vs prefetched next plane's registers
// KEY CHANGE vs R11: after LOAD(n), ALL z/y diffs of the current plane are
// computed BEFORE any use of n (x-diffs last) -> ~40 instructions of latency
// cover between the LDGs and their first consumer, at zero added cost.

#define ROW    385u
#define PLANE  148225u
#define NZT    13u                 // z tiles: zb = 0,31,...,372
#define NYG    55u                 // y groups of 7 owned rows
#define XC     8u                  // x chunks of 48 planes
#define WPB    8u
#define NTASKS (NZT * NYG * XC)    // 5720 warp tasks
#define NBLOCKS (NTASKS / WPB)     // 715

__device__ double   g_part[NBLOCKS];
__device__ unsigned g_count = 0;

__global__ void __launch_bounds__(256, 5)
occ_main(const float* __restrict__ occ, float* __restrict__ out) {
    const unsigned wid  = threadIdx.x >> 5;
    const unsigned lane = threadIdx.x & 31u;

    const unsigned w  = blockIdx.x * WPB + wid;
    const unsigned zt = w % NZT;
    const unsigned r1 = w / NZT;
    const unsigned yg = r1 % NYG;
    const unsigned xc = r1 / NYG;

    const unsigned zb = zt * 31u;
    const unsigned z  = min(zb + lane, 384u);       // clamp: dup loads harmless
    const unsigned yb = yg * 7u;

    const bool lastzt = (zt == NZT - 1u);
    const bool yxm = lane < (lastzt ? 13u : 31u);   // owned z columns
    const bool zm  = lane < (lastzt ? 12u : 31u);   // owned z pairs

    const unsigned as    = 48u * xc;                // planes [as, as+48]
    const bool     lastc = (xc == XC - 1u);
    // last y group: row 7 duplicates row 6 (y=384) -> y-diff contributes 0
    const unsigned off7  = (yg == NYG - 1u) ? 6u * ROW : 7u * ROW;

    const float* p = occ + (size_t)yb * ROW + z + (size_t)as * PLANE;

    float s0 = 0.f, s1 = 0.f;
    float v[8], n[8];

    v[0]=__ldg(p);          v[1]=__ldg(p+ROW);      v[2]=__ldg(p+2u*ROW);
    v[3]=__ldg(p+3u*ROW);   v[4]=__ldg(p+4u*ROW);   v[5]=__ldg(p+5u*ROW);
    v[6]=__ldg(p+6u*ROW);   v[7]=__ldg(p+off7);

    #define LOAD(A) do { p += PLANE;                                        \
        A[0]=__ldg(p);        A[1]=__ldg(p+ROW);    A[2]=__ldg(p+2u*ROW);   \
        A[3]=__ldg(p+3u*ROW); A[4]=__ldg(p+4u*ROW); A[5]=__ldg(p+5u*ROW);   \
        A[6]=__ldg(p+6u*ROW); A[7]=__ldg(p+off7); } while(0)

    // z/y diffs of plane V — NO dependence on the in-flight loads
    #define ZYB(V) do {                                                     \
        _Pragma("unroll")                                                   \
        for (int r = 0; r < 7; ++r) {                                       \
            float zn = __shfl_down_sync(0xffffffffu, V[r], 1);              \
            float dz = fabsf(zn - V[r]);                                    \
            float dy = fabsf(V[r+1] - V[r]);                                \
            if (zm)  s0 += dz;                                              \
            if (yxm) s0 += dy;                                              \
        } } while(0)

    // x-diffs pair (V, N) — first consumer of the freshly loaded N
    #define XB(V,N) do {                                                    \
        _Pragma("unroll")                                                   \
        for (int r = 0; r < 7; ++r) {                                       \
            float dx = fabsf(N[r] - V[r]);                                  \
            if (yxm) s1 += dx;                                              \
        } } while(0)

    // 48 x-pairs per chunk; unrolled x2 with register-role swap (no moves)
    #pragma unroll 1
    for (int i = 0; i < 48; i += 2) {
        LOAD(n);
        ZYB(v);        // latency cover: no use of n here
        XB(v, n);
        LOAD(v);
        ZYB(n);        // latency cover: no use of v here
        XB(n, v);
    }

    // final plane x = 384 (last chunk only): z/y diffs, no x-diff
    if (lastc) ZYB(v);

    // ---- block reduction ----
    float s = s0 + s1;
    #pragma unroll
    for (int o = 16; o > 0; o >>= 1)
        s += __shfl_down_sync(0xffffffffu, s, o);

    __shared__ float    ws[WPB];
    __shared__ unsigned islast_s;
    if (lane == 0u) ws[wid] = s;
    __syncthreads();
    if (threadIdx.x == 0u) {
        float t = 0.f;
        #pragma unroll
        for (unsigned i = 0; i < WPB; ++i) t += ws[i];
        g_part[blockIdx.x] = (double)t;
        __threadfence();
        unsigned old = atomicAdd(&g_count, 1u);
        islast_s = (old == NBLOCKS - 1u) ? 1u : 0u;
    }
    __syncthreads();

    // ---- last block folds partials (single launch total) ----
    if (islast_s) {
        double d = 0.0;
        for (unsigned i = threadIdx.x; i < NBLOCKS; i += 256u)
            d += g_part[i];
        __shared__ double dsm[256];
        dsm[threadIdx.x] = d;
        __syncthreads();
        #pragma unroll
        for (int st = 128; st > 0; st >>= 1) {
            if ((int)threadIdx.x < st) dsm[threadIdx.x] += dsm[threadIdx.x + st];
            __syncthreads();
        }
        if (threadIdx.x == 0u) {
            out[0] = (float)dsm[0];
            g_count = 0u;   // reset for next graph replay
        }
    }
}

extern "C" void kernel_launch(void* const* d_in, const int* in_sizes, int n_in,
                              void* d_out, int out_size) {
    const float* occ = (const float*)d_in[0];
    float* out = (float*)d_out;
    occ_main<<<NBLOCKS, 256>>>(occ, out);
}